// round 3
// baseline (speedup 1.0000x reference)
#include <cuda_runtime.h>
#include <math.h>

#define B_    2
#define C_    256
#define NTOK  9216
#define L_    6

#define BR 64
#define BC 64

// ---------------- scratch (no allocations allowed) ----------------
__device__ float g_Wf[L_*C_*C_];     // BN-folded weights
__device__ float g_bf[L_*C_];        // BN-folded bias
__device__ float g_t  [B_*C_*NTOK];  // temp (psi1 / phi1)
__device__ float g_q  [B_*C_*NTOK];  // psi2 out  [B][C][N]
__device__ float g_k  [B_*C_*NTOK];  // phi2 out  [B][C][N]
__device__ float g_v  [B_*C_*NTOK];  // f_down out [B][C][N]
__device__ float g_ctx[B_*C_*NTOK];  // attention out [B][C][N]

// ---------------- prep: fold BN into W and bias ----------------
// convbn(x) = (s*W) @ x + (b - m*s), s = g*rsqrt(v+eps)
__global__ void prep_kernel(const float* __restrict__ Ws, const float* __restrict__ gam,
                            const float* __restrict__ bet, const float* __restrict__ mu,
                            const float* __restrict__ var) {
    int l = blockIdx.x;
    int tid = threadIdx.x;
    __shared__ float sc[C_];
    float s = gam[l*C_+tid] * rsqrtf(var[l*C_+tid] + 1e-5f);
    sc[tid] = s;
    g_bf[l*C_+tid] = bet[l*C_+tid] - mu[l*C_+tid]*s;
    __syncthreads();
    const float* Wl = Ws + l*C_*C_;
    float*       Wo = g_Wf + l*C_*C_;
    for (int t = tid; t < C_*C_; t += blockDim.x) {
        Wo[t] = Wl[t] * sc[t >> 8];
    }
}

// ---------------- fused convbn+relu GEMM ----------------
// out[b][o][n] = relu( sum_c Wf[o][c]*in[b][c][n] + bf[o] )
// Tile: 64(o) x 128(n), K-step 16, 256 threads, 4x8 per thread.
__global__ __launch_bounds__(256) void convbn_kernel(const float* __restrict__ in,
                                                     float* __restrict__ out, int layer) {
    const float* Wf = g_Wf + layer*C_*C_;
    const float* bf = g_bf + layer*C_;
    const int n0 = blockIdx.x * 128;
    const int o0 = blockIdx.y * 64;
    const float* inb  = in  + (size_t)blockIdx.z * C_ * NTOK;
    float*       outb = out + (size_t)blockIdx.z * C_ * NTOK;

    __shared__ float As[16][64];    // [k][o]
    __shared__ float Bs[16][128];   // [k][n]

    const int tid = threadIdx.x;
    const int tx = tid & 15, ty = tid >> 4;

    float acc[4][8];
#pragma unroll
    for (int i = 0; i < 4; i++)
#pragma unroll
        for (int j = 0; j < 8; j++) acc[i][j] = 0.f;

    const int oA = tid >> 2, cA = (tid & 3) << 2;
    const int bRow = tid >> 5, bCol4 = (tid & 31);

    for (int c0 = 0; c0 < C_; c0 += 16) {
        // prefetch global into regs (overlaps with previous tile's compute)
        float4 w  = *(const float4*)&Wf[(o0+oA)*C_ + c0 + cA];
        float4 b0 = *(const float4*)&inb[(size_t)(c0 + bRow    )*NTOK + n0 + bCol4*4];
        float4 b1 = *(const float4*)&inb[(size_t)(c0 + 8 + bRow)*NTOK + n0 + bCol4*4];
        __syncthreads();
        As[cA+0][oA] = w.x; As[cA+1][oA] = w.y; As[cA+2][oA] = w.z; As[cA+3][oA] = w.w;
        *(float4*)&Bs[bRow    ][bCol4*4] = b0;
        *(float4*)&Bs[8 + bRow][bCol4*4] = b1;
        __syncthreads();
#pragma unroll
        for (int k = 0; k < 16; k++) {
            float4 a = *(const float4*)&As[k][ty*4];
            float4 p = *(const float4*)&Bs[k][tx*8];
            float4 q = *(const float4*)&Bs[k][tx*8+4];
            float av[4] = {a.x, a.y, a.z, a.w};
            float bv[8] = {p.x, p.y, p.z, p.w, q.x, q.y, q.z, q.w};
#pragma unroll
            for (int i = 0; i < 4; i++)
#pragma unroll
                for (int j = 0; j < 8; j++)
                    acc[i][j] = fmaf(av[i], bv[j], acc[i][j]);
        }
    }

#pragma unroll
    for (int i = 0; i < 4; i++) {
        int o = o0 + ty*4 + i;
        float bias = bf[o];
        float4 r0, r1;
        r0.x = fmaxf(acc[i][0]+bias, 0.f);
        r0.y = fmaxf(acc[i][1]+bias, 0.f);
        r0.z = fmaxf(acc[i][2]+bias, 0.f);
        r0.w = fmaxf(acc[i][3]+bias, 0.f);
        r1.x = fmaxf(acc[i][4]+bias, 0.f);
        r1.y = fmaxf(acc[i][5]+bias, 0.f);
        r1.z = fmaxf(acc[i][6]+bias, 0.f);
        r1.w = fmaxf(acc[i][7]+bias, 0.f);
        *(float4*)&outb[(size_t)o*NTOK + n0 + tx*8    ] = r0;
        *(float4*)&outb[(size_t)o*NTOK + n0 + tx*8 + 4] = r1;
    }
}

// ---------------- flash attention (fp32, online softmax) ----------------
// q,k,v stored [B][C=256][N].  sim[n,m] = sum_c q[c,n]k[c,m]; softmax over m;
// ctx[c,n] = sum_m p[n,m] v[c,m].  One CTA = 64 query rows; loops all 9216 keys.
#define ATTN_SMEM_FLOATS (256*64 + 256*64 + 64*260 + 64*65 + 64*16 + 3*64)

__global__ __launch_bounds__(256) void attn_kernel(const float* __restrict__ qg,
                                                   const float* __restrict__ kg,
                                                   const float* __restrict__ vg,
                                                   float* __restrict__ cg) {
    extern __shared__ float smf[];
    float* sQ  = smf;               // [256][64]  (row k, col i)
    float* sK  = sQ + 256*64;       // [256][64]  (row k, col j)
    float* sV  = sK + 256*64;       // [64][260]  (row j, col k')  (transposed, padded)
    float* sP  = sV + 64*260;       // [64][65]   (row j, col i)
    float* red = sP + 64*65;        // [64][16]   partial max / partial sum
    float* m_s = red + 64*16;       // [64] running max
    float* l_s = m_s + 64;          // [64] running sum
    float* fac = l_s + 64;          // [64] rescale factor

    const int n0 = blockIdx.x * BR;
    const size_t boff = (size_t)blockIdx.y * C_ * NTOK;
    const float* qb = qg + boff;
    const float* kb = kg + boff;
    const float* vb = vg + boff;
    float*       cb = cg + boff;

    const int tid = threadIdx.x;
    const int tx = tid & 15, ty = tid >> 4;
    const int i0 = ty * 4, j0 = tx * 4;
    const int jg = tid & 15, kb16 = tid >> 4;

    // load Q tile once: sQ[k][i]
#pragma unroll
    for (int rep = 0; rep < 16; rep++) {
        int k = kb16 + rep*16;
        *(float4*)&sQ[k*64 + jg*4] = *(const float4*)&qb[(size_t)k*NTOK + n0 + jg*4];
    }
    if (tid < 64) { m_s[tid] = -1e30f; l_s[tid] = 0.f; }

    float o_acc[4][16];
#pragma unroll
    for (int i = 0; i < 4; i++)
#pragma unroll
        for (int c = 0; c < 16; c++) o_acc[i][c] = 0.f;

    __syncthreads();

    for (int t = 0; t < NTOK/BC; t++) {
        const int m0 = t * BC;
        // ---- load K tile [k][j] and V tile transposed [j][k'] ----
#pragma unroll
        for (int rep = 0; rep < 16; rep++) {
            int k = kb16 + rep*16;
            *(float4*)&sK[k*64 + jg*4] = *(const float4*)&kb[(size_t)k*NTOK + m0 + jg*4];
        }
#pragma unroll
        for (int rep = 0; rep < 16; rep++) {
            int k = kb16 + rep*16;
            float4 vl = *(const float4*)&vb[(size_t)k*NTOK + m0 + jg*4];
            sV[(jg*4+0)*260 + k] = vl.x;
            sV[(jg*4+1)*260 + k] = vl.y;
            sV[(jg*4+2)*260 + k] = vl.z;
            sV[(jg*4+3)*260 + k] = vl.w;
        }
        __syncthreads();

        // ---- S = Q^T K  (4x4 per thread) ----
        float s[4][4];
#pragma unroll
        for (int i = 0; i < 4; i++)
#pragma unroll
            for (int j = 0; j < 4; j++) s[i][j] = 0.f;

#pragma unroll 4
        for (int k = 0; k < 256; k++) {
            float4 a = *(const float4*)&sQ[k*64 + i0];
            float4 b = *(const float4*)&sK[k*64 + j0];
            s[0][0] = fmaf(a.x, b.x, s[0][0]); s[0][1] = fmaf(a.x, b.y, s[0][1]);
            s[0][2] = fmaf(a.x, b.z, s[0][2]); s[0][3] = fmaf(a.x, b.w, s[0][3]);
            s[1][0] = fmaf(a.y, b.x, s[1][0]); s[1][1] = fmaf(a.y, b.y, s[1][1]);
            s[1][2] = fmaf(a.y, b.z, s[1][2]); s[1][3] = fmaf(a.y, b.w, s[1][3]);
            s[2][0] = fmaf(a.z, b.x, s[2][0]); s[2][1] = fmaf(a.z, b.y, s[2][1]);
            s[2][2] = fmaf(a.z, b.z, s[2][2]); s[2][3] = fmaf(a.z, b.w, s[2][3]);
            s[3][0] = fmaf(a.w, b.x, s[3][0]); s[3][1] = fmaf(a.w, b.y, s[3][1]);
            s[3][2] = fmaf(a.w, b.z, s[3][2]); s[3][3] = fmaf(a.w, b.w, s[3][3]);
        }

        // ---- row-max partials ----
#pragma unroll
        for (int i = 0; i < 4; i++) {
            float lm = fmaxf(fmaxf(s[i][0], s[i][1]), fmaxf(s[i][2], s[i][3]));
            red[(i0+i)*16 + tx] = lm;
        }
        __syncthreads();
        if (tid < 64) {
            float mt = red[tid*16];
#pragma unroll
            for (int u = 1; u < 16; u++) mt = fmaxf(mt, red[tid*16+u]);
            float mo = m_s[tid];
            float mn = fmaxf(mo, mt);
            m_s[tid] = mn;
            fac[tid] = __expf(mo - mn);
        }
        __syncthreads();

        // ---- exp, write P^T, partial sums ----
#pragma unroll
        for (int i = 0; i < 4; i++) {
            float mi = m_s[i0+i];
            float ps = 0.f;
#pragma unroll
            for (int j = 0; j < 4; j++) {
                float p = __expf(s[i][j] - mi);
                sP[(j0+j)*65 + i0 + i] = p;
                ps += p;
            }
            red[(i0+i)*16 + tx] = ps;
        }
        __syncthreads();
        if (tid < 64) {
            float st = 0.f;
#pragma unroll
            for (int u = 0; u < 16; u++) st += red[tid*16+u];
            l_s[tid] = l_s[tid]*fac[tid] + st;
        }

        // ---- rescale O (fac stable: written 2 syncs ago) ----
        float f0 = fac[i0+0], f1 = fac[i0+1], f2 = fac[i0+2], f3 = fac[i0+3];
#pragma unroll
        for (int c = 0; c < 16; c++) {
            o_acc[0][c] *= f0; o_acc[1][c] *= f1;
            o_acc[2][c] *= f2; o_acc[3][c] *= f3;
        }

        // ---- O += P V   (4 rows x 16 k' per thread) ----
#pragma unroll 2
        for (int j = 0; j < BC; j++) {
            float p0 = sP[j*65 + i0    ];
            float p1 = sP[j*65 + i0 + 1];
            float p2 = sP[j*65 + i0 + 2];
            float p3 = sP[j*65 + i0 + 3];
#pragma unroll
            for (int c = 0; c < 4; c++) {
                float4 v4 = *(const float4*)&sV[j*260 + tx*4 + c*64];
                o_acc[0][c*4+0] = fmaf(p0, v4.x, o_acc[0][c*4+0]);
                o_acc[0][c*4+1] = fmaf(p0, v4.y, o_acc[0][c*4+1]);
                o_acc[0][c*4+2] = fmaf(p0, v4.z, o_acc[0][c*4+2]);
                o_acc[0][c*4+3] = fmaf(p0, v4.w, o_acc[0][c*4+3]);
                o_acc[1][c*4+0] = fmaf(p1, v4.x, o_acc[1][c*4+0]);
                o_acc[1][c*4+1] = fmaf(p1, v4.y, o_acc[1][c*4+1]);
                o_acc[1][c*4+2] = fmaf(p1, v4.z, o_acc[1][c*4+2]);
                o_acc[1][c*4+3] = fmaf(p1, v4.w, o_acc[1][c*4+3]);
                o_acc[2][c*4+0] = fmaf(p2, v4.x, o_acc[2][c*4+0]);
                o_acc[2][c*4+1] = fmaf(p2, v4.y, o_acc[2][c*4+1]);
                o_acc[2][c*4+2] = fmaf(p2, v4.z, o_acc[2][c*4+2]);
                o_acc[2][c*4+3] = fmaf(p2, v4.w, o_acc[2][c*4+3]);
                o_acc[3][c*4+0] = fmaf(p3, v4.x, o_acc[3][c*4+0]);
                o_acc[3][c*4+1] = fmaf(p3, v4.y, o_acc[3][c*4+1]);
                o_acc[3][c*4+2] = fmaf(p3, v4.z, o_acc[3][c*4+2]);
                o_acc[3][c*4+3] = fmaf(p3, v4.w, o_acc[3][c*4+3]);
            }
        }
        __syncthreads();
    }

    // ---- finalize: divide by l, write ctx[k'][n] ----
    float inv0 = 1.f / l_s[i0+0];
    float inv1 = 1.f / l_s[i0+1];
    float inv2 = 1.f / l_s[i0+2];
    float inv3 = 1.f / l_s[i0+3];
#pragma unroll
    for (int c = 0; c < 4; c++) {
#pragma unroll
        for (int cc = 0; cc < 4; cc++) {
            int kcol = c*64 + tx*4 + cc;
            float4 r;
            r.x = o_acc[0][c*4+cc] * inv0;
            r.y = o_acc[1][c*4+cc] * inv1;
            r.z = o_acc[2][c*4+cc] * inv2;
            r.w = o_acc[3][c*4+cc] * inv3;
            *(float4*)&cb[(size_t)kcol*NTOK + n0 + i0] = r;
        }
    }
}

// ---------------- launch ----------------
extern "C" void kernel_launch(void* const* d_in, const int* in_sizes, int n_in,
                              void* d_out, int out_size) {
    const float* x   = (const float*)d_in[0];
    const float* fk  = (const float*)d_in[1];
    const float* Ws  = (const float*)d_in[2];
    const float* gam = (const float*)d_in[3];
    const float* bet = (const float*)d_in[4];
    const float* mu  = (const float*)d_in[5];
    const float* var = (const float*)d_in[6];
    float* out = (float*)d_out;

    float *p_t, *p_q, *p_k, *p_v, *p_ctx;
    cudaGetSymbolAddress((void**)&p_t,   g_t);
    cudaGetSymbolAddress((void**)&p_q,   g_q);
    cudaGetSymbolAddress((void**)&p_k,   g_k);
    cudaGetSymbolAddress((void**)&p_v,   g_v);
    cudaGetSymbolAddress((void**)&p_ctx, g_ctx);

    const int attn_smem = ATTN_SMEM_FLOATS * 4;   // 219,136 B
    cudaFuncSetAttribute(attn_kernel, cudaFuncAttributeMaxDynamicSharedMemorySize, attn_smem);

    prep_kernel<<<L_, 256>>>(Ws, gam, bet, mu, var);

    dim3 cgrid(NTOK/128, C_/64, B_);
    convbn_kernel<<<cgrid, 256>>>(x,     p_t, 0);   // psi1
    convbn_kernel<<<cgrid, 256>>>(p_t,   p_q, 1);   // psi2  -> q
    convbn_kernel<<<cgrid, 256>>>(fk,    p_t, 2);   // phi1
    convbn_kernel<<<cgrid, 256>>>(p_t,   p_k, 3);   // phi2  -> k
    convbn_kernel<<<cgrid, 256>>>(fk,    p_v, 4);   // f_down -> v

    attn_kernel<<<dim3(NTOK/BR, B_), 256, attn_smem>>>(p_q, p_k, p_v, p_ctx);

    convbn_kernel<<<cgrid, 256>>>(p_ctx, out, 5);   // f_up -> output
}